// round 14
// baseline (speedup 1.0000x reference)
#include <cuda_runtime.h>

// Problem constants
#define BB 256      // batch
#define TT 2000     // seq len
#define HH 64       // hidden
#define G4 256      // 4*H
#define VV 2000     // vocab

// Scratch (allocation-free rule: __device__ globals)
__device__ float g_proj[(size_t)VV * G4];   // [v][j] fp32, 2 MB (L2-resident)
__device__ float g_hf[BB * HH];

typedef unsigned long long u64;

__device__ __forceinline__ u64 fma2(u64 a, u64 b, u64 c) {
    u64 d;
    asm("fma.rn.f32x2 %0, %1, %2, %3;" : "=l"(d) : "l"(a), "l"(b), "l"(c));
    return d;
}
__device__ __forceinline__ u64 add2(u64 a, u64 b) {
    u64 d;
    asm("add.rn.f32x2 %0, %1, %2;" : "=l"(d) : "l"(a), "l"(b));
    return d;
}
__device__ __forceinline__ u64 pack2(float lo, float hi) {
    u64 d;
    asm("mov.b64 %0, {%1, %2};" : "=l"(d) : "f"(lo), "f"(hi));
    return d;
}
__device__ __forceinline__ float hsum2(u64 a) {
    float lo, hi;
    asm("mov.b64 {%0, %1}, %2;" : "=f"(lo), "=f"(hi) : "l"(a));
    return lo + hi;
}
__device__ __forceinline__ float ex2_(float x) {
    float r; asm("ex2.approx.f32 %0, %1;" : "=f"(r) : "f"(x)); return r;
}
__device__ __forceinline__ float rcp_(float x) {
    float r; asm("rcp.approx.f32 %0, %1;" : "=f"(r) : "f"(x)); return r;
}
__device__ __forceinline__ float tanha_(float x) {
    float r; asm("tanh.approx.f32 %0, %1;" : "=f"(r) : "f"(x)); return r;
}
__device__ __forceinline__ float sigmoid_(float x) {
    return rcp_(1.0f + ex2_(-1.4426950408889634f * x));
}
__device__ __forceinline__ float tanh_(float x) {
    return fmaf(2.0f, rcp_(1.0f + ex2_(-2.8853900817779268f * x)), -1.0f);
}

// no-op kernels: keep ncu's capture slot (-s 5 -c 1) on k_scan (our 4th launch)
__global__ void k_nop() {}

// ---------------------------------------------------------------------------
// K0: proj[v][j] = sum_k emb[v][k] * w_ih_f[j][k] + b_ih_f[j] + b_hh_f[j]
// (unscaled — k_scan applies the sigmoid pre-scale, exactly as in R7)
// ---------------------------------------------------------------------------
__global__ void __launch_bounds__(256) k_proj(
    const float* __restrict__ emb, const float* __restrict__ w,
    const float* __restrict__ b1, const float* __restrict__ b2)
{
    __shared__ __align__(16) float sh_e[8 * 64];
    const int j = threadIdx.x;

    u64 w2[32];
#pragma unroll
    for (int k2 = 0; k2 < 32; ++k2) {
        float2 wv = *(const float2*)&w[j * 64 + 2 * k2];
        w2[k2] = pack2(wv.x, wv.y);
    }
    const float bias = b1[j] + b2[j];

    const int v0 = blockIdx.x * 8;
#pragma unroll
    for (int i = j; i < 512; i += 256) {
        int r = i >> 6, k = i & 63;
        int v = v0 + r;
        sh_e[i] = (v == 0 || v >= VV) ? 0.0f : emb[v * HH + k];
    }
    __syncthreads();
    const ulonglong2* ep = (const ulonglong2*)sh_e;
#pragma unroll
    for (int r = 0; r < 8; ++r) {
        int v = v0 + r;
        if (v >= VV) break;
        u64 acc = 0ull;
#pragma unroll
        for (int k4 = 0; k4 < 16; ++k4) {
            ulonglong2 ev = ep[r * 16 + k4];
            acc = fma2(w2[2 * k4], ev.x, acc);
            acc = fma2(w2[2 * k4 + 1], ev.y, acc);
        }
        g_proj[(size_t)v * G4 + j] = hsum2(acc) + bias;
    }
}

// ---------------------------------------------------------------------------
// K2: forward LSTM scan — EXACT R7 body + one-time anti-phase delay for odd
// CTAs. 256 CTAs x 128 threads, one batch row per CTA, 2 co-resident per SM.
// The two co-resident CTAs have identical per-step duration, so their
// relative phase is near-neutral: starting them ~half a step apart should
// let each fill the other's chain stalls for all 2000 steps.
// ---------------------------------------------------------------------------
__global__ void __launch_bounds__(128, 2) k_scan(
    const int* __restrict__ x, const float* __restrict__ whh)
{
    __shared__ __align__(16) float h_sh[2][64];  // [buf][unit]
    __shared__ int xs[TT];                       // this row's indices, 8 KB
    const int tid = threadIdx.x;
    const int w = tid >> 5, l = tid & 31;
    const int gate = l & 3;                // 0:i 1:f 2:g 3:o
    const int u0 = 2 * (w * 8 + (l >> 2)); // even unit 0..62
    const int b = blockIdx.x;
    const int j0 = gate * 64 + u0;         // adjacent pair j0, j0+1

    // stage x indices
    {
        const int* xr = x + (size_t)b * TT;
        for (int i = tid; i < TT; i += 128) xs[i] = xr[i];
    }

    // gate==2 (candidate) uses tanh(p); others sigmoid(p)=0.5*tanh(0.5p)+0.5.
    const float sg = (gate == 2) ? 1.0f : 0.5f;
    const float mv = (gate == 2) ? 1.0f : 0.5f;
    const float av = (gate == 2) ? 0.0f : 0.5f;

    // weight rows j0, j0+1 in registers (k-packed f32x2), pre-scaled by sg
    u64 wa[32], wb[32];
#pragma unroll
    for (int k2 = 0; k2 < 32; ++k2) {
        float2 va = *(const float2*)&whh[j0 * 64 + 2 * k2];
        float2 vb = *(const float2*)&whh[(j0 + 1) * 64 + 2 * k2];
        wa[k2] = pack2(sg * va.x, sg * va.y);
        wb[k2] = pack2(sg * vb.x, sg * vb.y);
    }

    // zero step-0 read buffer
    if (tid < 64) h_sh[0][tid] = 0.0f;
    float c0 = 0.0f, c1 = 0.0f;

    const float* __restrict__ proj = g_proj;

    __syncthreads();  // x stage + h init visible

    // ---- anti-phase offset: odd CTAs burn ~300 cyc once (half a step) ----
    // Dependent-FMA chain, not removable by DCE (result feeds a never-true
    // store through data the compiler can't constant-fold).
    if (b & 1) {
        float z = whh[0];
#pragma unroll
        for (int i = 0; i < 75; ++i) z = fmaf(z, 1.0000001f, 1.0f);
        if (__float_as_uint(z) == 0xdeadbeefu) h_sh[0][0] = z;
    }

    // distance-2 prefetch of input projections (L2-resident table), pre-scaled
    float2 v01 = *(const float2*)&proj[xs[0] * G4 + j0];
    float2 v11 = *(const float2*)&proj[xs[1] * G4 + j0];
    float xc0 = sg * v01.x, xc1 = sg * v01.y;
    float xn0 = sg * v11.x, xn1 = sg * v11.y;

    for (int t = 0; t < TT - 1; ++t) {
        int tp = min(t + 2, TT - 1);      // clamp, branch-free
        float2 xv = *(const float2*)&proj[xs[tp] * G4 + j0];
        float xf0 = sg * xv.x, xf1 = sg * xv.y;

        // recurrent dots: p = h . (sg*whh[j]) + xc  (8-deep f32x2 chains)
        const ulonglong2* hp = (const ulonglong2*)h_sh[t & 1];
        u64 a0 = 0ull, a1 = 0ull, a2 = 0ull, a3 = 0ull;
        u64 d0 = 0ull, d1 = 0ull, d2 = 0ull, d3 = 0ull;
#pragma unroll
        for (int k4 = 0; k4 < 8; ++k4) {
            ulonglong2 hv0 = hp[k4];
            ulonglong2 hv1 = hp[8 + k4];
            a0 = fma2(wa[2 * k4],      hv0.x, a0);
            a1 = fma2(wa[2 * k4 + 1],  hv0.y, a1);
            a2 = fma2(wa[16 + 2 * k4], hv1.x, a2);
            a3 = fma2(wa[17 + 2 * k4], hv1.y, a3);
            d0 = fma2(wb[2 * k4],      hv0.x, d0);
            d1 = fma2(wb[2 * k4 + 1],  hv0.y, d1);
            d2 = fma2(wb[16 + 2 * k4], hv1.x, d2);
            d3 = fma2(wb[17 + 2 * k4], hv1.y, d3);
        }
        float p0 = hsum2(add2(add2(a0, a1), add2(a2, a3))) + xc0;
        float p1 = hsum2(add2(add2(d0, d1), add2(d2, d3))) + xc1;

        // one-MUFU activation
        float v0 = fmaf(mv, tanha_(p0), av);
        float v1 = fmaf(mv, tanha_(p1), av);

        // quad exchange: gate0 lanes get (f,g,o); others wrapped garbage
        float f0 = __shfl_down_sync(0xffffffffu, v0, 1);
        float g0 = __shfl_down_sync(0xffffffffu, v0, 2);
        float o0 = __shfl_down_sync(0xffffffffu, v0, 3);
        float f1 = __shfl_down_sync(0xffffffffu, v1, 1);
        float g1 = __shfl_down_sync(0xffffffffu, v1, 2);
        float o1 = __shfl_down_sync(0xffffffffu, v1, 3);

        // unconditional cell update (garbage off-lanes never stored)
        c0 = f0 * c0 + v0 * g0;
        c1 = f1 * c1 + v1 * g1;
        float2 hv;
        hv.x = o0 * tanha_(c0);
        hv.y = o1 * tanha_(c1);
        if (gate == 0)                      // single predicated STS.64
            *(float2*)&h_sh[(t + 1) & 1][u0] = hv;
        __syncthreads();

        xc0 = xn0; xc1 = xn1; xn0 = xf0; xn1 = xf1;
    }

    // peeled final step t = TT-1: write h straight to global
    {
        const ulonglong2* hp = (const ulonglong2*)h_sh[(TT - 1) & 1];
        u64 a0 = 0ull, a1 = 0ull, a2 = 0ull, a3 = 0ull;
        u64 d0 = 0ull, d1 = 0ull, d2 = 0ull, d3 = 0ull;
#pragma unroll
        for (int k4 = 0; k4 < 8; ++k4) {
            ulonglong2 hv0 = hp[k4];
            ulonglong2 hv1 = hp[8 + k4];
            a0 = fma2(wa[2 * k4],      hv0.x, a0);
            a1 = fma2(wa[2 * k4 + 1],  hv0.y, a1);
            a2 = fma2(wa[16 + 2 * k4], hv1.x, a2);
            a3 = fma2(wa[17 + 2 * k4], hv1.y, a3);
            d0 = fma2(wb[2 * k4],      hv0.x, d0);
            d1 = fma2(wb[2 * k4 + 1],  hv0.y, d1);
            d2 = fma2(wb[16 + 2 * k4], hv1.x, d2);
            d3 = fma2(wb[17 + 2 * k4], hv1.y, d3);
        }
        float p0 = hsum2(add2(add2(a0, a1), add2(a2, a3))) + xc0;
        float p1 = hsum2(add2(add2(d0, d1), add2(d2, d3))) + xc1;
        float v0 = fmaf(mv, tanha_(p0), av);
        float v1 = fmaf(mv, tanha_(p1), av);
        float f0 = __shfl_down_sync(0xffffffffu, v0, 1);
        float g0 = __shfl_down_sync(0xffffffffu, v0, 2);
        float o0 = __shfl_down_sync(0xffffffffu, v0, 3);
        float f1 = __shfl_down_sync(0xffffffffu, v1, 1);
        float g1 = __shfl_down_sync(0xffffffffu, v1, 2);
        float o1 = __shfl_down_sync(0xffffffffu, v1, 3);
        c0 = f0 * c0 + v0 * g0;
        c1 = f1 * c1 + v1 * g1;
        float2 hv;
        hv.x = o0 * tanha_(c0);
        hv.y = o1 * tanha_(c1);
        if (gate == 0)
            *(float2*)&g_hf[b * HH + u0] = hv;
    }
}

// ---------------------------------------------------------------------------
// K3: fused tail. One block per batch row:
//   1) backward LSTM single step (hs_b[0]) from zero state at t=T-1
//   2) fc: out[b][c] = concat(hf[b], hb[b]) . w_fc[c] + b_fc[c]
// ---------------------------------------------------------------------------
__global__ void __launch_bounds__(256) k_tail(
    const int* __restrict__ x, const float* __restrict__ emb,
    const float* __restrict__ w, const float* __restrict__ b1,
    const float* __restrict__ b2, const float* __restrict__ wfc,
    const float* __restrict__ bfc, float* __restrict__ out)
{
    __shared__ __align__(16) float e_sh[64];
    __shared__ float g_sh[256];
    __shared__ float hb_sh[64];
    const int j = threadIdx.x;
    const int b = blockIdx.x;

    if (j < 64) {
        int idx = x[b * TT + (TT - 1)];
        e_sh[j] = (idx == 0) ? 0.0f : emb[idx * HH + j];
    }
    __syncthreads();

    float acc = b1[j] + b2[j];
    const ulonglong2* ep = (const ulonglong2*)e_sh;
    u64 a2 = 0ull;
#pragma unroll
    for (int k4 = 0; k4 < 16; ++k4) {
        float2 wv0 = *(const float2*)&w[j * 64 + 4 * k4];
        float2 wv1 = *(const float2*)&w[j * 64 + 4 * k4 + 2];
        ulonglong2 ev = ep[k4];
        a2 = fma2(pack2(wv0.x, wv0.y), ev.x, a2);
        a2 = fma2(pack2(wv1.x, wv1.y), ev.y, a2);
    }
    acc += hsum2(a2);

    const int gate = j >> 6;
    g_sh[j] = (gate == 2) ? tanh_(acc) : sigmoid_(acc);
    __syncthreads();

    if (j < 64) {
        float iv = g_sh[j];
        float gv = g_sh[128 + j];
        float ov = g_sh[192 + j];
        float cc = iv * gv;               // f*c0 = 0
        hb_sh[j] = ov * tanh_(cc);
    }
    __syncthreads();

    if (j < 12) {
        float s = bfc[j];
        const float* hf = g_hf + b * HH;
#pragma unroll
        for (int k = 0; k < 64; ++k)
            s += hf[k] * wfc[j * 128 + k];
#pragma unroll
        for (int k = 0; k < 64; ++k)
            s += hb_sh[k] * wfc[j * 128 + 64 + k];
        out[b * 12 + j] = s;
    }
}

// ---------------------------------------------------------------------------
extern "C" void kernel_launch(void* const* d_in, const int* in_sizes, int n_in,
                              void* d_out, int out_size)
{
    const int*   x      = (const int*)d_in[0];
    const float* emb    = (const float*)d_in[1];
    const float* w_ih_f = (const float*)d_in[2];
    const float* w_hh_f = (const float*)d_in[3];
    const float* b_ih_f = (const float*)d_in[4];
    const float* b_hh_f = (const float*)d_in[5];
    const float* w_ih_b = (const float*)d_in[6];
    const float* w_hh_b = (const float*)d_in[7];
    const float* b_ih_b = (const float*)d_in[8];
    const float* b_hh_b = (const float*)d_in[9];
    const float* w_fc   = (const float*)d_in[10];
    const float* b_fc   = (const float*)d_in[11];
    float* out = (float*)d_out;

    k_proj<<<(VV + 7) / 8, 256>>>(emb, w_ih_f, b_ih_f, b_hh_f);
    k_nop<<<1, 32>>>();   // slot alignment: keep k_scan as our 4th launch
    k_nop<<<1, 32>>>();   // so ncu (-s 5 -c 1) captures it
    k_scan<<<BB, 128>>>(x, w_hh_f);
    k_tail<<<BB, 256>>>(x, emb, w_ih_b, b_ih_b, b_hh_b, w_fc, b_fc, out);
}

// round 15
// speedup vs baseline: 1.0777x; 1.0777x over previous
#include <cuda_runtime.h>

// Problem constants
#define BB 256      // batch
#define TT 2000     // seq len
#define HH 64       // hidden
#define G4 256      // 4*H
#define VV 2000     // vocab

// Scratch (allocation-free rule: __device__ globals)
__device__ float g_proj[(size_t)VV * G4];   // [v][j] fp32, 2 MB (L2-resident)
__device__ float g_hf[BB * HH];

typedef unsigned long long u64;

__device__ __forceinline__ u64 fma2(u64 a, u64 b, u64 c) {
    u64 d;
    asm("fma.rn.f32x2 %0, %1, %2, %3;" : "=l"(d) : "l"(a), "l"(b), "l"(c));
    return d;
}
__device__ __forceinline__ u64 add2(u64 a, u64 b) {
    u64 d;
    asm("add.rn.f32x2 %0, %1, %2;" : "=l"(d) : "l"(a), "l"(b));
    return d;
}
__device__ __forceinline__ u64 pack2(float lo, float hi) {
    u64 d;
    asm("mov.b64 %0, {%1, %2};" : "=l"(d) : "f"(lo), "f"(hi));
    return d;
}
__device__ __forceinline__ float hsum2(u64 a) {
    float lo, hi;
    asm("mov.b64 {%0, %1}, %2;" : "=f"(lo), "=f"(hi) : "l"(a));
    return lo + hi;
}
__device__ __forceinline__ float ex2_(float x) {
    float r; asm("ex2.approx.f32 %0, %1;" : "=f"(r) : "f"(x)); return r;
}
__device__ __forceinline__ float rcp_(float x) {
    float r; asm("rcp.approx.f32 %0, %1;" : "=f"(r) : "f"(x)); return r;
}
__device__ __forceinline__ float tanha_(float x) {
    float r; asm("tanh.approx.f32 %0, %1;" : "=f"(r) : "f"(x)); return r;
}
__device__ __forceinline__ float sigmoid_(float x) {
    return rcp_(1.0f + ex2_(-1.4426950408889634f * x));
}
__device__ __forceinline__ float tanh_(float x) {
    return fmaf(2.0f, rcp_(1.0f + ex2_(-2.8853900817779268f * x)), -1.0f);
}

// ---------------------------------------------------------------------------
// K0: proj[v][j] = sum_k emb[v][k] * w_ih_f[j][k] + b_ih_f[j] + b_hh_f[j]
// ---------------------------------------------------------------------------
__global__ void __launch_bounds__(256) k_proj(
    const float* __restrict__ emb, const float* __restrict__ w,
    const float* __restrict__ b1, const float* __restrict__ b2)
{
    __shared__ __align__(16) float sh_e[8 * 64];
    const int j = threadIdx.x;

    u64 w2[32];
#pragma unroll
    for (int k2 = 0; k2 < 32; ++k2) {
        float2 wv = *(const float2*)&w[j * 64 + 2 * k2];
        w2[k2] = pack2(wv.x, wv.y);
    }
    const float bias = b1[j] + b2[j];

    const int v0 = blockIdx.x * 8;
#pragma unroll
    for (int i = j; i < 512; i += 256) {
        int r = i >> 6, k = i & 63;
        int v = v0 + r;
        sh_e[i] = (v == 0 || v >= VV) ? 0.0f : emb[v * HH + k];
    }
    __syncthreads();
    const ulonglong2* ep = (const ulonglong2*)sh_e;
#pragma unroll
    for (int r = 0; r < 8; ++r) {
        int v = v0 + r;
        if (v >= VV) break;
        u64 acc = 0ull;
#pragma unroll
        for (int k4 = 0; k4 < 16; ++k4) {
            ulonglong2 ev = ep[r * 16 + k4];
            acc = fma2(w2[2 * k4], ev.x, acc);
            acc = fma2(w2[2 * k4 + 1], ev.y, acc);
        }
        g_proj[(size_t)v * G4 + j] = hsum2(acc) + bias;
    }
}

// ---------------------------------------------------------------------------
// K2: forward LSTM scan.
// 256 CTAs x 128 threads, ONE batch row per CTA, 2 CTAs co-resident per SM
// (independent barriers/chains hide each other's latency). Quad-gate lanes:
// gate = l&3, unit pair (u0, u0+1) with u0 = 2*(w*8 + l>>2) -> adjacent j
// so proj prefetch is one LDG.64 and h stores are 64-bit. Cell update
// computed unconditionally in every lane (wrapped-shfl garbage in non-gate0
// lanes is never stored); only the STS is predicated -> no BSSY/BSYNC.
// ---------------------------------------------------------------------------
__global__ void __launch_bounds__(128, 2) k_scan(
    const int* __restrict__ x, const float* __restrict__ whh)
{
    __shared__ __align__(16) float h_sh[2][64];  // [buf][unit]
    __shared__ int xs[TT];                       // this row's indices, 8 KB
    const int tid = threadIdx.x;
    const int w = tid >> 5, l = tid & 31;
    const int gate = l & 3;                // 0:i 1:f 2:g 3:o
    const int u0 = 2 * (w * 8 + (l >> 2)); // even unit 0..62
    const int b = blockIdx.x;
    const int j0 = gate * 64 + u0;         // adjacent pair j0, j0+1

    // stage x indices
    {
        const int* xr = x + (size_t)b * TT;
        for (int i = tid; i < TT; i += 128) xs[i] = xr[i];
    }

    // gate==2 (candidate) uses tanh(p); others sigmoid(p)=0.5*tanh(0.5p)+0.5.
    const float sg = (gate == 2) ? 1.0f : 0.5f;
    const float mv = (gate == 2) ? 1.0f : 0.5f;
    const float av = (gate == 2) ? 0.0f : 0.5f;

    // weight rows j0, j0+1 in registers (k-packed f32x2), pre-scaled by sg
    u64 wa[32], wb[32];
#pragma unroll
    for (int k2 = 0; k2 < 32; ++k2) {
        float2 va = *(const float2*)&whh[j0 * 64 + 2 * k2];
        float2 vb = *(const float2*)&whh[(j0 + 1) * 64 + 2 * k2];
        wa[k2] = pack2(sg * va.x, sg * va.y);
        wb[k2] = pack2(sg * vb.x, sg * vb.y);
    }

    // zero step-0 read buffer
    if (tid < 64) h_sh[0][tid] = 0.0f;
    float c0 = 0.0f, c1 = 0.0f;

    const float* __restrict__ proj = g_proj;

    __syncthreads();  // x stage + h init visible

    // distance-2 prefetch of input projections (L2-resident table), pre-scaled
    float2 v01 = *(const float2*)&proj[xs[0] * G4 + j0];
    float2 v11 = *(const float2*)&proj[xs[1] * G4 + j0];
    float xc0 = sg * v01.x, xc1 = sg * v01.y;
    float xn0 = sg * v11.x, xn1 = sg * v11.y;

    for (int t = 0; t < TT - 1; ++t) {
        int tp = min(t + 2, TT - 1);      // clamp, branch-free
        float2 xv = *(const float2*)&proj[xs[tp] * G4 + j0];
        float xf0 = sg * xv.x, xf1 = sg * xv.y;

        // recurrent dots: p = h . (sg*whh[j]) + xc  (8-deep f32x2 chains)
        const ulonglong2* hp = (const ulonglong2*)h_sh[t & 1];
        u64 a0 = 0ull, a1 = 0ull, a2 = 0ull, a3 = 0ull;
        u64 d0 = 0ull, d1 = 0ull, d2 = 0ull, d3 = 0ull;
#pragma unroll
        for (int k4 = 0; k4 < 8; ++k4) {
            ulonglong2 hv0 = hp[k4];
            ulonglong2 hv1 = hp[8 + k4];
            a0 = fma2(wa[2 * k4],      hv0.x, a0);
            a1 = fma2(wa[2 * k4 + 1],  hv0.y, a1);
            a2 = fma2(wa[16 + 2 * k4], hv1.x, a2);
            a3 = fma2(wa[17 + 2 * k4], hv1.y, a3);
            d0 = fma2(wb[2 * k4],      hv0.x, d0);
            d1 = fma2(wb[2 * k4 + 1],  hv0.y, d1);
            d2 = fma2(wb[16 + 2 * k4], hv1.x, d2);
            d3 = fma2(wb[17 + 2 * k4], hv1.y, d3);
        }
        float p0 = hsum2(add2(add2(a0, a1), add2(a2, a3))) + xc0;
        float p1 = hsum2(add2(add2(d0, d1), add2(d2, d3))) + xc1;

        // one-MUFU activation
        float v0 = fmaf(mv, tanha_(p0), av);
        float v1 = fmaf(mv, tanha_(p1), av);

        // quad exchange: gate0 lanes get (f,g,o); others wrapped garbage
        float f0 = __shfl_down_sync(0xffffffffu, v0, 1);
        float g0 = __shfl_down_sync(0xffffffffu, v0, 2);
        float o0 = __shfl_down_sync(0xffffffffu, v0, 3);
        float f1 = __shfl_down_sync(0xffffffffu, v1, 1);
        float g1 = __shfl_down_sync(0xffffffffu, v1, 2);
        float o1 = __shfl_down_sync(0xffffffffu, v1, 3);

        // unconditional cell update (garbage off-lanes never stored)
        c0 = f0 * c0 + v0 * g0;
        c1 = f1 * c1 + v1 * g1;
        float2 hv;
        hv.x = o0 * tanha_(c0);
        hv.y = o1 * tanha_(c1);
        if (gate == 0)                      // single predicated STS.64
            *(float2*)&h_sh[(t + 1) & 1][u0] = hv;
        __syncthreads();

        xc0 = xn0; xc1 = xn1; xn0 = xf0; xn1 = xf1;
    }

    // peeled final step t = TT-1: write h straight to global
    {
        const ulonglong2* hp = (const ulonglong2*)h_sh[(TT - 1) & 1];
        u64 a0 = 0ull, a1 = 0ull, a2 = 0ull, a3 = 0ull;
        u64 d0 = 0ull, d1 = 0ull, d2 = 0ull, d3 = 0ull;
#pragma unroll
        for (int k4 = 0; k4 < 8; ++k4) {
            ulonglong2 hv0 = hp[k4];
            ulonglong2 hv1 = hp[8 + k4];
            a0 = fma2(wa[2 * k4],      hv0.x, a0);
            a1 = fma2(wa[2 * k4 + 1],  hv0.y, a1);
            a2 = fma2(wa[16 + 2 * k4], hv1.x, a2);
            a3 = fma2(wa[17 + 2 * k4], hv1.y, a3);
            d0 = fma2(wb[2 * k4],      hv0.x, d0);
            d1 = fma2(wb[2 * k4 + 1],  hv0.y, d1);
            d2 = fma2(wb[16 + 2 * k4], hv1.x, d2);
            d3 = fma2(wb[17 + 2 * k4], hv1.y, d3);
        }
        float p0 = hsum2(add2(add2(a0, a1), add2(a2, a3))) + xc0;
        float p1 = hsum2(add2(add2(d0, d1), add2(d2, d3))) + xc1;
        float v0 = fmaf(mv, tanha_(p0), av);
        float v1 = fmaf(mv, tanha_(p1), av);
        float f0 = __shfl_down_sync(0xffffffffu, v0, 1);
        float g0 = __shfl_down_sync(0xffffffffu, v0, 2);
        float o0 = __shfl_down_sync(0xffffffffu, v0, 3);
        float f1 = __shfl_down_sync(0xffffffffu, v1, 1);
        float g1 = __shfl_down_sync(0xffffffffu, v1, 2);
        float o1 = __shfl_down_sync(0xffffffffu, v1, 3);
        c0 = f0 * c0 + v0 * g0;
        c1 = f1 * c1 + v1 * g1;
        float2 hv;
        hv.x = o0 * tanha_(c0);
        hv.y = o1 * tanha_(c1);
        if (gate == 0)
            *(float2*)&g_hf[b * HH + u0] = hv;
    }
}

// ---------------------------------------------------------------------------
// K3: fused tail. One block per batch row:
//   1) backward LSTM single step (hs_b[0]) from zero state at t=T-1
//   2) fc: out[b][c] = concat(hf[b], hb[b]) . w_fc[c] + b_fc[c]
// ---------------------------------------------------------------------------
__global__ void __launch_bounds__(256) k_tail(
    const int* __restrict__ x, const float* __restrict__ emb,
    const float* __restrict__ w, const float* __restrict__ b1,
    const float* __restrict__ b2, const float* __restrict__ wfc,
    const float* __restrict__ bfc, float* __restrict__ out)
{
    __shared__ __align__(16) float e_sh[64];
    __shared__ float g_sh[256];
    __shared__ float hb_sh[64];
    const int j = threadIdx.x;
    const int b = blockIdx.x;

    if (j < 64) {
        int idx = x[b * TT + (TT - 1)];
        e_sh[j] = (idx == 0) ? 0.0f : emb[idx * HH + j];
    }
    __syncthreads();

    float acc = b1[j] + b2[j];
    const ulonglong2* ep = (const ulonglong2*)e_sh;
    u64 a2 = 0ull;
#pragma unroll
    for (int k4 = 0; k4 < 16; ++k4) {
        float2 wv0 = *(const float2*)&w[j * 64 + 4 * k4];
        float2 wv1 = *(const float2*)&w[j * 64 + 4 * k4 + 2];
        ulonglong2 ev = ep[k4];
        a2 = fma2(pack2(wv0.x, wv0.y), ev.x, a2);
        a2 = fma2(pack2(wv1.x, wv1.y), ev.y, a2);
    }
    acc += hsum2(a2);

    const int gate = j >> 6;
    g_sh[j] = (gate == 2) ? tanh_(acc) : sigmoid_(acc);
    __syncthreads();

    if (j < 64) {
        float iv = g_sh[j];
        float gv = g_sh[128 + j];
        float ov = g_sh[192 + j];
        float cc = iv * gv;               // f*c0 = 0
        hb_sh[j] = ov * tanh_(cc);
    }
    __syncthreads();

    if (j < 12) {
        float s = bfc[j];
        const float* hf = g_hf + b * HH;
#pragma unroll
        for (int k = 0; k < 64; ++k)
            s += hf[k] * wfc[j * 128 + k];
#pragma unroll
        for (int k = 0; k < 64; ++k)
            s += hb_sh[k] * wfc[j * 128 + 64 + k];
        out[b * 12 + j] = s;
    }
}

// ---------------------------------------------------------------------------
extern "C" void kernel_launch(void* const* d_in, const int* in_sizes, int n_in,
                              void* d_out, int out_size)
{
    const int*   x      = (const int*)d_in[0];
    const float* emb    = (const float*)d_in[1];
    const float* w_ih_f = (const float*)d_in[2];
    const float* w_hh_f = (const float*)d_in[3];
    const float* b_ih_f = (const float*)d_in[4];
    const float* b_hh_f = (const float*)d_in[5];
    const float* w_ih_b = (const float*)d_in[6];
    const float* w_hh_b = (const float*)d_in[7];
    const float* b_ih_b = (const float*)d_in[8];
    const float* b_hh_b = (const float*)d_in[9];
    const float* w_fc   = (const float*)d_in[10];
    const float* b_fc   = (const float*)d_in[11];
    float* out = (float*)d_out;

    k_proj<<<(VV + 7) / 8, 256>>>(emb, w_ih_f, b_ih_f, b_hh_f);
    k_scan<<<BB, 128>>>(x, w_hh_f);
    k_tail<<<BB, 256>>>(x, emb, w_ih_b, b_ih_b, b_hh_b, w_fc, b_fc, out);
}

// round 17
// speedup vs baseline: 1.0873x; 1.0090x over previous
#include <cuda_runtime.h>

// Problem constants
#define BB 256      // batch
#define TT 2000     // seq len
#define HH 64       // hidden
#define G4 256      // 4*H
#define VV 2000     // vocab

// Scratch (allocation-free rule: __device__ globals)
__device__ float g_proj[(size_t)VV * G4];   // [v][j] fp32, 2 MB (L2-resident)
__device__ float g_hf[BB * HH];

typedef unsigned long long u64;

__device__ __forceinline__ u64 fma2(u64 a, u64 b, u64 c) {
    u64 d;
    asm("fma.rn.f32x2 %0, %1, %2, %3;" : "=l"(d) : "l"(a), "l"(b), "l"(c));
    return d;
}
__device__ __forceinline__ u64 add2(u64 a, u64 b) {
    u64 d;
    asm("add.rn.f32x2 %0, %1, %2;" : "=l"(d) : "l"(a), "l"(b));
    return d;
}
__device__ __forceinline__ u64 pack2(float lo, float hi) {
    u64 d;
    asm("mov.b64 %0, {%1, %2};" : "=l"(d) : "f"(lo), "f"(hi));
    return d;
}
__device__ __forceinline__ float hsum2(u64 a) {
    float lo, hi;
    asm("mov.b64 {%0, %1}, %2;" : "=f"(lo), "=f"(hi) : "l"(a));
    return lo + hi;
}
__device__ __forceinline__ float ex2_(float x) {
    float r; asm("ex2.approx.f32 %0, %1;" : "=f"(r) : "f"(x)); return r;
}
__device__ __forceinline__ float rcp_(float x) {
    float r; asm("rcp.approx.f32 %0, %1;" : "=f"(r) : "f"(x)); return r;
}
__device__ __forceinline__ float tanha_(float x) {
    float r; asm("tanh.approx.f32 %0, %1;" : "=f"(r) : "f"(x)); return r;
}
__device__ __forceinline__ float sigmoid_(float x) {
    return rcp_(1.0f + ex2_(-1.4426950408889634f * x));
}
__device__ __forceinline__ float tanh_(float x) {
    return fmaf(2.0f, rcp_(1.0f + ex2_(-2.8853900817779268f * x)), -1.0f);
}

// ---------------------------------------------------------------------------
// K0: proj[v][j] = sum_k emb[v][k] * w_ih_f[j][k] + b_ih_f[j] + b_hh_f[j]
// 16 vocab rows per CTA -> grid 125 = ONE wave on 148 SMs (2000 = 125*16,
// no bounds checks). Accumulation chain token-identical to the 8-row
// version, so proj values are bit-identical.
// ---------------------------------------------------------------------------
__global__ void __launch_bounds__(256) k_proj(
    const float* __restrict__ emb, const float* __restrict__ w,
    const float* __restrict__ b1, const float* __restrict__ b2)
{
    __shared__ __align__(16) float sh_e[16 * 64];   // 4 KB
    const int j = threadIdx.x;

    u64 w2[32];
#pragma unroll
    for (int k2 = 0; k2 < 32; ++k2) {
        float2 wv = *(const float2*)&w[j * 64 + 2 * k2];
        w2[k2] = pack2(wv.x, wv.y);
    }
    const float bias = b1[j] + b2[j];

    const int v0 = blockIdx.x * 16;
#pragma unroll
    for (int i = j; i < 1024; i += 256) {
        int r = i >> 6, k = i & 63;
        int v = v0 + r;
        sh_e[i] = (v == 0) ? 0.0f : emb[v * HH + k];
    }
    __syncthreads();
    const ulonglong2* ep = (const ulonglong2*)sh_e;
#pragma unroll
    for (int r = 0; r < 16; ++r) {
        int v = v0 + r;
        u64 acc = 0ull;
#pragma unroll
        for (int k4 = 0; k4 < 16; ++k4) {
            ulonglong2 ev = ep[r * 16 + k4];
            acc = fma2(w2[2 * k4], ev.x, acc);
            acc = fma2(w2[2 * k4 + 1], ev.y, acc);
        }
        g_proj[(size_t)v * G4 + j] = hsum2(acc) + bias;
    }
}

// ---------------------------------------------------------------------------
// K2: forward LSTM scan.  [FROZEN — byte-identical to the 637.0 us build]
// 256 CTAs x 128 threads, ONE batch row per CTA, 2 CTAs co-resident per SM
// (independent barriers/chains hide each other's latency). Quad-gate lanes:
// gate = l&3, unit pair (u0, u0+1) with u0 = 2*(w*8 + l>>2) -> adjacent j
// so proj prefetch is one LDG.64 and h stores are 64-bit. Cell update
// computed unconditionally in every lane (wrapped-shfl garbage in non-gate0
// lanes is never stored); only the STS is predicated -> no BSSY/BSYNC.
// ---------------------------------------------------------------------------
__global__ void __launch_bounds__(128, 2) k_scan(
    const int* __restrict__ x, const float* __restrict__ whh)
{
    __shared__ __align__(16) float h_sh[2][64];  // [buf][unit]
    __shared__ int xs[TT];                       // this row's indices, 8 KB
    const int tid = threadIdx.x;
    const int w = tid >> 5, l = tid & 31;
    const int gate = l & 3;                // 0:i 1:f 2:g 3:o
    const int u0 = 2 * (w * 8 + (l >> 2)); // even unit 0..62
    const int b = blockIdx.x;
    const int j0 = gate * 64 + u0;         // adjacent pair j0, j0+1

    // stage x indices
    {
        const int* xr = x + (size_t)b * TT;
        for (int i = tid; i < TT; i += 128) xs[i] = xr[i];
    }

    // gate==2 (candidate) uses tanh(p); others sigmoid(p)=0.5*tanh(0.5p)+0.5.
    const float sg = (gate == 2) ? 1.0f : 0.5f;
    const float mv = (gate == 2) ? 1.0f : 0.5f;
    const float av = (gate == 2) ? 0.0f : 0.5f;

    // weight rows j0, j0+1 in registers (k-packed f32x2), pre-scaled by sg
    u64 wa[32], wb[32];
#pragma unroll
    for (int k2 = 0; k2 < 32; ++k2) {
        float2 va = *(const float2*)&whh[j0 * 64 + 2 * k2];
        float2 vb = *(const float2*)&whh[(j0 + 1) * 64 + 2 * k2];
        wa[k2] = pack2(sg * va.x, sg * va.y);
        wb[k2] = pack2(sg * vb.x, sg * vb.y);
    }

    // zero step-0 read buffer
    if (tid < 64) h_sh[0][tid] = 0.0f;
    float c0 = 0.0f, c1 = 0.0f;

    const float* __restrict__ proj = g_proj;

    __syncthreads();  // x stage + h init visible

    // distance-2 prefetch of input projections (L2-resident table), pre-scaled
    float2 v01 = *(const float2*)&proj[xs[0] * G4 + j0];
    float2 v11 = *(const float2*)&proj[xs[1] * G4 + j0];
    float xc0 = sg * v01.x, xc1 = sg * v01.y;
    float xn0 = sg * v11.x, xn1 = sg * v11.y;

    for (int t = 0; t < TT - 1; ++t) {
        int tp = min(t + 2, TT - 1);      // clamp, branch-free
        float2 xv = *(const float2*)&proj[xs[tp] * G4 + j0];
        float xf0 = sg * xv.x, xf1 = sg * xv.y;

        // recurrent dots: p = h . (sg*whh[j]) + xc  (8-deep f32x2 chains)
        const ulonglong2* hp = (const ulonglong2*)h_sh[t & 1];
        u64 a0 = 0ull, a1 = 0ull, a2 = 0ull, a3 = 0ull;
        u64 d0 = 0ull, d1 = 0ull, d2 = 0ull, d3 = 0ull;
#pragma unroll
        for (int k4 = 0; k4 < 8; ++k4) {
            ulonglong2 hv0 = hp[k4];
            ulonglong2 hv1 = hp[8 + k4];
            a0 = fma2(wa[2 * k4],      hv0.x, a0);
            a1 = fma2(wa[2 * k4 + 1],  hv0.y, a1);
            a2 = fma2(wa[16 + 2 * k4], hv1.x, a2);
            a3 = fma2(wa[17 + 2 * k4], hv1.y, a3);
            d0 = fma2(wb[2 * k4],      hv0.x, d0);
            d1 = fma2(wb[2 * k4 + 1],  hv0.y, d1);
            d2 = fma2(wb[16 + 2 * k4], hv1.x, d2);
            d3 = fma2(wb[17 + 2 * k4], hv1.y, d3);
        }
        float p0 = hsum2(add2(add2(a0, a1), add2(a2, a3))) + xc0;
        float p1 = hsum2(add2(add2(d0, d1), add2(d2, d3))) + xc1;

        // one-MUFU activation
        float v0 = fmaf(mv, tanha_(p0), av);
        float v1 = fmaf(mv, tanha_(p1), av);

        // quad exchange: gate0 lanes get (f,g,o); others wrapped garbage
        float f0 = __shfl_down_sync(0xffffffffu, v0, 1);
        float g0 = __shfl_down_sync(0xffffffffu, v0, 2);
        float o0 = __shfl_down_sync(0xffffffffu, v0, 3);
        float f1 = __shfl_down_sync(0xffffffffu, v1, 1);
        float g1 = __shfl_down_sync(0xffffffffu, v1, 2);
        float o1 = __shfl_down_sync(0xffffffffu, v1, 3);

        // unconditional cell update (garbage off-lanes never stored)
        c0 = f0 * c0 + v0 * g0;
        c1 = f1 * c1 + v1 * g1;
        float2 hv;
        hv.x = o0 * tanha_(c0);
        hv.y = o1 * tanha_(c1);
        if (gate == 0)                      // single predicated STS.64
            *(float2*)&h_sh[(t + 1) & 1][u0] = hv;
        __syncthreads();

        xc0 = xn0; xc1 = xn1; xn0 = xf0; xn1 = xf1;
    }

    // peeled final step t = TT-1: write h straight to global
    {
        const ulonglong2* hp = (const ulonglong2*)h_sh[(TT - 1) & 1];
        u64 a0 = 0ull, a1 = 0ull, a2 = 0ull, a3 = 0ull;
        u64 d0 = 0ull, d1 = 0ull, d2 = 0ull, d3 = 0ull;
#pragma unroll
        for (int k4 = 0; k4 < 8; ++k4) {
            ulonglong2 hv0 = hp[k4];
            ulonglong2 hv1 = hp[8 + k4];
            a0 = fma2(wa[2 * k4],      hv0.x, a0);
            a1 = fma2(wa[2 * k4 + 1],  hv0.y, a1);
            a2 = fma2(wa[16 + 2 * k4], hv1.x, a2);
            a3 = fma2(wa[17 + 2 * k4], hv1.y, a3);
            d0 = fma2(wb[2 * k4],      hv0.x, d0);
            d1 = fma2(wb[2 * k4 + 1],  hv0.y, d1);
            d2 = fma2(wb[16 + 2 * k4], hv1.x, d2);
            d3 = fma2(wb[17 + 2 * k4], hv1.y, d3);
        }
        float p0 = hsum2(add2(add2(a0, a1), add2(a2, a3))) + xc0;
        float p1 = hsum2(add2(add2(d0, d1), add2(d2, d3))) + xc1;
        float v0 = fmaf(mv, tanha_(p0), av);
        float v1 = fmaf(mv, tanha_(p1), av);
        float f0 = __shfl_down_sync(0xffffffffu, v0, 1);
        float g0 = __shfl_down_sync(0xffffffffu, v0, 2);
        float o0 = __shfl_down_sync(0xffffffffu, v0, 3);
        float f1 = __shfl_down_sync(0xffffffffu, v1, 1);
        float g1 = __shfl_down_sync(0xffffffffu, v1, 2);
        float o1 = __shfl_down_sync(0xffffffffu, v1, 3);
        c0 = f0 * c0 + v0 * g0;
        c1 = f1 * c1 + v1 * g1;
        float2 hv;
        hv.x = o0 * tanha_(c0);
        hv.y = o1 * tanha_(c1);
        if (gate == 0)
            *(float2*)&g_hf[b * HH + u0] = hv;
    }
}

// ---------------------------------------------------------------------------
// K3: fused tail.  [FROZEN — byte-identical to the 637.0 us build]
// One block per batch row:
//   1) backward LSTM single step (hs_b[0]) from zero state at t=T-1
//   2) fc: out[b][c] = concat(hf[b], hb[b]) . w_fc[c] + b_fc[c]
// ---------------------------------------------------------------------------
__global__ void __launch_bounds__(256) k_tail(
    const int* __restrict__ x, const float* __restrict__ emb,
    const float* __restrict__ w, const float* __restrict__ b1,
    const float* __restrict__ b2, const float* __restrict__ wfc,
    const float* __restrict__ bfc, float* __restrict__ out)
{
    __shared__ __align__(16) float e_sh[64];
    __shared__ float g_sh[256];
    __shared__ float hb_sh[64];
    const int j = threadIdx.x;
    const int b = blockIdx.x;

    if (j < 64) {
        int idx = x[b * TT + (TT - 1)];
        e_sh[j] = (idx == 0) ? 0.0f : emb[idx * HH + j];
    }
    __syncthreads();

    float acc = b1[j] + b2[j];
    const ulonglong2* ep = (const ulonglong2*)e_sh;
    u64 a2 = 0ull;
#pragma unroll
    for (int k4 = 0; k4 < 16; ++k4) {
        float2 wv0 = *(const float2*)&w[j * 64 + 4 * k4];
        float2 wv1 = *(const float2*)&w[j * 64 + 4 * k4 + 2];
        ulonglong2 ev = ep[k4];
        a2 = fma2(pack2(wv0.x, wv0.y), ev.x, a2);
        a2 = fma2(pack2(wv1.x, wv1.y), ev.y, a2);
    }
    acc += hsum2(a2);

    const int gate = j >> 6;
    g_sh[j] = (gate == 2) ? tanh_(acc) : sigmoid_(acc);
    __syncthreads();

    if (j < 64) {
        float iv = g_sh[j];
        float gv = g_sh[128 + j];
        float ov = g_sh[192 + j];
        float cc = iv * gv;               // f*c0 = 0
        hb_sh[j] = ov * tanh_(cc);
    }
    __syncthreads();

    if (j < 12) {
        float s = bfc[j];
        const float* hf = g_hf + b * HH;
#pragma unroll
        for (int k = 0; k < 64; ++k)
            s += hf[k] * wfc[j * 128 + k];
#pragma unroll
        for (int k = 0; k < 64; ++k)
            s += hb_sh[k] * wfc[j * 128 + 64 + k];
        out[b * 12 + j] = s;
    }
}

// ---------------------------------------------------------------------------
extern "C" void kernel_launch(void* const* d_in, const int* in_sizes, int n_in,
                              void* d_out, int out_size)
{
    const int*   x      = (const int*)d_in[0];
    const float* emb    = (const float*)d_in[1];
    const float* w_ih_f = (const float*)d_in[2];
    const float* w_hh_f = (const float*)d_in[3];
    const float* b_ih_f = (const float*)d_in[4];
    const float* b_hh_f = (const float*)d_in[5];
    const float* w_ih_b = (const float*)d_in[6];
    const float* w_hh_b = (const float*)d_in[7];
    const float* b_ih_b = (const float*)d_in[8];
    const float* b_hh_b = (const float*)d_in[9];
    const float* w_fc   = (const float*)d_in[10];
    const float* b_fc   = (const float*)d_in[11];
    float* out = (float*)d_out;

    k_proj<<<VV / 16, 256>>>(emb, w_ih_f, b_ih_f, b_hh_f);
    k_scan<<<BB, 128>>>(x, w_hh_f);
    k_tail<<<BB, 256>>>(x, emb, w_ih_b, b_ih_b, b_hh_b, w_fc, b_fc, out);
}